// round 4
// baseline (speedup 1.0000x reference)
#include <cuda_runtime.h>

// Problem constants
#define B_   4
#define TQ_  512
#define TKV_ 4096
#define D_   1024
#define H_   8
#define HD_  128

// Scratch (device globals; no allocation allowed)
__device__ float g_Q[(size_t)B_ * TQ_ * D_];    // 8 MB
__device__ float g_K[(size_t)B_ * TKV_ * D_];   // 64 MB
__device__ float g_V[(size_t)B_ * TKV_ * D_];   // 64 MB
__device__ float g_A[(size_t)B_ * TQ_ * D_];    // 8 MB (attention output, pre-Wo)
__device__ unsigned char g_M[(size_t)B_ * TQ_ * TKV_];  // 8 MB canonical mask
__device__ int g_mask_mode;                     // 0=uint8, 1=int32, 2=float32

// ---------------------------------------------------------------------------
// Mask dtype detection: scan first 64KB of the raw mask buffer.
//  - byte value > 1 anywhere           -> float32 encoding (bytes 0x80/0x3f)
//  - nonzero byte at offset i%4 != 0   -> genuine uint8 0/1 data
//  - otherwise                          -> int32 0/1 (only lowest byte nonzero)
// Single block; deterministic; writes g_mask_mode.
// ---------------------------------------------------------------------------
__global__ void detect_mask_kernel(const unsigned char* __restrict__ m)
{
    __shared__ int s_weird, s_misal;
    if (threadIdx.x == 0) { s_weird = 0; s_misal = 0; }
    __syncthreads();
    int w = 0, ma = 0;
    for (int i = threadIdx.x * 4; i < 65536; i += 256 * 4) {
        uchar4 v = *(const uchar4*)(m + i);      // v.x at offset i (i%4==0)
        if (v.x > 1 || v.y > 1 || v.z > 1 || v.w > 1) w = 1;
        if (v.y | v.z | v.w) ma = 1;
    }
    if (w)  atomicOr(&s_weird, 1);
    if (ma) atomicOr(&s_misal, 1);
    __syncthreads();
    if (threadIdx.x == 0)
        g_mask_mode = s_weird ? 2 : (s_misal ? 0 : 1);
}

// ---------------------------------------------------------------------------
// Convert raw mask (whatever encoding) to canonical uint8 0/1 in g_M.
// 4 elements per thread, exact cover: 8388608 / 4 = 2097152 threads.
// ---------------------------------------------------------------------------
__global__ __launch_bounds__(256) void convert_mask_kernel(const void* __restrict__ src)
{
    const size_t i4 = ((size_t)blockIdx.x * blockDim.x + threadIdx.x) * 4;
    const int mode = g_mask_mode;
    uchar4 o;
    if (mode == 0) {
        uchar4 v = *(const uchar4*)((const unsigned char*)src + i4);
        o.x = v.x ? 1 : 0; o.y = v.y ? 1 : 0; o.z = v.z ? 1 : 0; o.w = v.w ? 1 : 0;
    } else if (mode == 1) {
        int4 v = *(const int4*)((const int*)src + i4);
        o.x = v.x ? 1 : 0; o.y = v.y ? 1 : 0; o.z = v.z ? 1 : 0; o.w = v.w ? 1 : 0;
    } else {
        float4 v = *(const float4*)((const float*)src + i4);
        o.x = (v.x != 0.f) ? 1 : 0; o.y = (v.y != 0.f) ? 1 : 0;
        o.z = (v.z != 0.f) ? 1 : 0; o.w = (v.w != 0.f) ? 1 : 0;
    }
    *(uchar4*)(g_M + i4) = o;
}

// ---------------------------------------------------------------------------
// GEMM: Y[M,N] = X[M,K] @ W[K,N] + bias[N]
// Tiles: BM=128, BN=64, BK=16. 256 threads, each computes 8x4.
// ---------------------------------------------------------------------------
__global__ __launch_bounds__(256) void gemm_bias_kernel(
    const float* __restrict__ X, const float* __restrict__ W,
    const float* __restrict__ bias, float* __restrict__ Y,
    int M, int N, int K)
{
    __shared__ float As[16][128];   // transposed A tile: As[k][m]
    __shared__ float Bs[16][64];    // Bs[k][n]

    const int tid = threadIdx.x;
    const int tx = tid & 15;
    const int ty = tid >> 4;
    const int m0 = blockIdx.y * 128;
    const int n0 = blockIdx.x * 64;

    const int ar = tid >> 2;              // 0..63
    const int ac = (tid & 3) << 2;        // 0,4,8,12
    const int br = tid >> 4;              // 0..15
    const int bc = (tid & 15) << 2;       // 0..60

    const float* Xp  = X + (size_t)(m0 + ar) * K + ac;
    const float* Xp2 = Xp + (size_t)64 * K;
    const float* Wp  = W + (size_t)br * N + n0 + bc;

    float acc[8][4] = {};

    float4 a0 = *(const float4*)(Xp);
    float4 a1 = *(const float4*)(Xp2);
    float4 b0 = *(const float4*)(Wp);

    for (int k0 = 0; k0 < K; k0 += 16) {
        __syncthreads();
        As[ac + 0][ar] = a0.x; As[ac + 1][ar] = a0.y;
        As[ac + 2][ar] = a0.z; As[ac + 3][ar] = a0.w;
        As[ac + 0][ar + 64] = a1.x; As[ac + 1][ar + 64] = a1.y;
        As[ac + 2][ar + 64] = a1.z; As[ac + 3][ar + 64] = a1.w;
        *(float4*)&Bs[br][bc] = b0;
        __syncthreads();

        if (k0 + 16 < K) {
            a0 = *(const float4*)(Xp + k0 + 16);
            a1 = *(const float4*)(Xp2 + k0 + 16);
            b0 = *(const float4*)(Wp + (size_t)(k0 + 16) * N);
        }

        #pragma unroll
        for (int kk = 0; kk < 16; kk++) {
            float4 av0 = *(float4*)&As[kk][ty * 8];
            float4 av1 = *(float4*)&As[kk][ty * 8 + 4];
            float4 bv  = *(float4*)&Bs[kk][tx * 4];
            float a8[8] = {av0.x, av0.y, av0.z, av0.w, av1.x, av1.y, av1.z, av1.w};
            float b4[4] = {bv.x, bv.y, bv.z, bv.w};
            #pragma unroll
            for (int i = 0; i < 8; i++)
                #pragma unroll
                for (int j = 0; j < 4; j++)
                    acc[i][j] += a8[i] * b4[j];
        }
    }

    float4 bb = *(const float4*)(bias + n0 + (tx << 2));
    #pragma unroll
    for (int r = 0; r < 8; r++) {
        float4 o;
        o.x = acc[r][0] + bb.x;
        o.y = acc[r][1] + bb.y;
        o.z = acc[r][2] + bb.z;
        o.w = acc[r][3] + bb.w;
        *(float4*)(Y + (size_t)(m0 + ty * 8 + r) * N + n0 + (tx << 2)) = o;
    }
}

// ---------------------------------------------------------------------------
// Flash attention, fp32, exact reference semantics.
// Block: one (b, h, 64-row q-tile). 256 threads (16x16).
// Masked scores = -1e30 (finite, matching jax); fully-masked rows wiped at end.
// ---------------------------------------------------------------------------
#define FLASH_SMEM_FLOATS (2 * 64 * 129 + 64 * 128 + 64 * 65)
#define FLASH_SMEM_BYTES  (FLASH_SMEM_FLOATS * 4)

__global__ __launch_bounds__(256) void flash_kernel(
    const float* __restrict__ Q, const float* __restrict__ Kg,
    const float* __restrict__ Vg, float* __restrict__ A)
{
    extern __shared__ float sm[];
    float* Qs = sm;                           // [64][129]
    float* Ks = sm + 64 * 129;                // [64][129]
    float* Vs = sm + 2 * 64 * 129;            // [64][128]
    float* Ps = sm + 2 * 64 * 129 + 64 * 128; // [64][65]  Ps[j][i]

    const int tid = threadIdx.x;
    const int tx = tid & 15;
    const int ty = tid >> 4;
    const int q0 = blockIdx.x * 64;
    const int h  = blockIdx.y;
    const int b  = blockIdx.z;

    const float SCALE = 0.08838834764831843f;  // 1/sqrt(128)
    const float NEG   = -1e30f;

    const float* Qb = Q  + ((size_t)b * TQ_ + q0) * D_ + h * HD_;
    const float* Kb = Kg + (size_t)b * TKV_ * D_ + h * HD_;
    const float* Vb = Vg + (size_t)b * TKV_ * D_ + h * HD_;
    const unsigned char* Mb = g_M + ((size_t)b * TQ_ + q0) * TKV_;

    // Load Q tile (64 x 128)
    #pragma unroll
    for (int r = 0; r < 8; r++) {
        int f = tid + 256 * r;
        int i = f >> 5;
        int d4 = (f & 31) << 2;
        float4 v = *(const float4*)(Qb + (size_t)i * D_ + d4);
        float* q = Qs + i * 129 + d4;
        q[0] = v.x; q[1] = v.y; q[2] = v.z; q[3] = v.w;
    }

    float m[4], l[4], acc[4][8];
    #pragma unroll
    for (int ii = 0; ii < 4; ii++) {
        m[ii] = -INFINITY;
        l[ii] = 0.0f;
        #pragma unroll
        for (int cc = 0; cc < 8; cc++) acc[ii][cc] = 0.0f;
    }

    for (int t = 0; t < TKV_ / 64; t++) {
        const int kv0 = t * 64;
        __syncthreads();

        const float* Kt = Kb + (size_t)kv0 * D_;
        const float* Vt = Vb + (size_t)kv0 * D_;
        #pragma unroll
        for (int r = 0; r < 8; r++) {
            int f = tid + 256 * r;
            int j = f >> 5;
            int d4 = (f & 31) << 2;
            float4 kv = *(const float4*)(Kt + (size_t)j * D_ + d4);
            float* kp = Ks + j * 129 + d4;
            kp[0] = kv.x; kp[1] = kv.y; kp[2] = kv.z; kp[3] = kv.w;
            float4 vv = *(const float4*)(Vt + (size_t)j * D_ + d4);
            *(float4*)(Vs + j * 128 + d4) = vv;
        }
        __syncthreads();

        // S = Q @ K^T  (4x4 per thread)
        float s[4][4] = {};
        const float* qrow = Qs + (ty * 4) * 129;
        const float* krow = Ks + (tx * 4) * 129;
        #pragma unroll 8
        for (int d = 0; d < 128; d++) {
            float qv[4], kv[4];
            #pragma unroll
            for (int ii = 0; ii < 4; ii++) qv[ii] = qrow[ii * 129 + d];
            #pragma unroll
            for (int jj = 0; jj < 4; jj++) kv[jj] = krow[jj * 129 + d];
            #pragma unroll
            for (int ii = 0; ii < 4; ii++)
                #pragma unroll
                for (int jj = 0; jj < 4; jj++)
                    s[ii][jj] += qv[ii] * kv[jj];
        }

        // Mask + scale
        #pragma unroll
        for (int ii = 0; ii < 4; ii++) {
            uchar4 mk = *(const uchar4*)(Mb + (size_t)(ty * 4 + ii) * TKV_ + kv0 + tx * 4);
            s[ii][0] = mk.x ? s[ii][0] * SCALE : NEG;
            s[ii][1] = mk.y ? s[ii][1] * SCALE : NEG;
            s[ii][2] = mk.z ? s[ii][2] * SCALE : NEG;
            s[ii][3] = mk.w ? s[ii][3] * SCALE : NEG;
        }

        // Online softmax (row reduction across 16 tx lanes via shfl_xor)
        #pragma unroll
        for (int ii = 0; ii < 4; ii++) {
            float rm = fmaxf(fmaxf(s[ii][0], s[ii][1]), fmaxf(s[ii][2], s[ii][3]));
            #pragma unroll
            for (int o = 1; o < 16; o <<= 1)
                rm = fmaxf(rm, __shfl_xor_sync(0xffffffffu, rm, o));
            float mnew = fmaxf(m[ii], rm);
            float corr = __expf(m[ii] - mnew);
            m[ii] = mnew;
            float rs = 0.0f;
            #pragma unroll
            for (int jj = 0; jj < 4; jj++) {
                float p = __expf(s[ii][jj] - mnew);
                s[ii][jj] = p;
                rs += p;
            }
            #pragma unroll
            for (int o = 1; o < 16; o <<= 1)
                rs += __shfl_xor_sync(0xffffffffu, rs, o);
            l[ii] = l[ii] * corr + rs;
            #pragma unroll
            for (int cc = 0; cc < 8; cc++) acc[ii][cc] *= corr;
        }

        // Write P transposed: Ps[j][i]
        #pragma unroll
        for (int jj = 0; jj < 4; jj++)
            #pragma unroll
            for (int ii = 0; ii < 4; ii++)
                Ps[(tx * 4 + jj) * 65 + ty * 4 + ii] = s[ii][jj];
        __syncthreads();

        // O += P @ V
        #pragma unroll 4
        for (int j = 0; j < 64; j++) {
            float p[4];
            #pragma unroll
            for (int ii = 0; ii < 4; ii++) p[ii] = Ps[j * 65 + ty * 4 + ii];
            float4 va = *(const float4*)(Vs + j * 128 + tx * 4);
            float4 vb = *(const float4*)(Vs + j * 128 + 64 + tx * 4);
            #pragma unroll
            for (int ii = 0; ii < 4; ii++) {
                acc[ii][0] += p[ii] * va.x;
                acc[ii][1] += p[ii] * va.y;
                acc[ii][2] += p[ii] * va.z;
                acc[ii][3] += p[ii] * va.w;
                acc[ii][4] += p[ii] * vb.x;
                acc[ii][5] += p[ii] * vb.y;
                acc[ii][6] += p[ii] * vb.z;
                acc[ii][7] += p[ii] * vb.w;
            }
        }
    }

    // Epilogue: normalize; wipe rows whose mask was entirely false.
    #pragma unroll
    for (int ii = 0; ii < 4; ii++) {
        float inv = (m[ii] < -1e29f) ? 0.0f : (1.0f / l[ii]);
        int qi = q0 + ty * 4 + ii;
        float* out = A + ((size_t)b * TQ_ + qi) * D_ + h * HD_ + tx * 4;
        float4 o1, o2;
        o1.x = acc[ii][0] * inv; o1.y = acc[ii][1] * inv;
        o1.z = acc[ii][2] * inv; o1.w = acc[ii][3] * inv;
        o2.x = acc[ii][4] * inv; o2.y = acc[ii][5] * inv;
        o2.z = acc[ii][6] * inv; o2.w = acc[ii][7] * inv;
        *(float4*)out = o1;
        *(float4*)(out + 64) = o2;
    }
}

// ---------------------------------------------------------------------------
// Launch: mask normalize + Q/K/V projections -> flash attention -> out proj.
// ---------------------------------------------------------------------------
extern "C" void kernel_launch(void* const* d_in, const int* in_sizes, int n_in,
                              void* d_out, int out_size)
{
    const float* xq   = (const float*)d_in[0];
    const float* xkv  = (const float*)d_in[1];
    const void*  mask = d_in[2];
    const float* Wq = (const float*)d_in[3];
    const float* bq = (const float*)d_in[4];
    const float* Wk = (const float*)d_in[5];
    const float* bk = (const float*)d_in[6];
    const float* Wv = (const float*)d_in[7];
    const float* bv = (const float*)d_in[8];
    const float* Wo = (const float*)d_in[9];
    const float* bo = (const float*)d_in[10];

    float *gQ, *gK, *gV, *gA;
    cudaGetSymbolAddress((void**)&gQ, g_Q);
    cudaGetSymbolAddress((void**)&gK, g_K);
    cudaGetSymbolAddress((void**)&gV, g_V);
    cudaGetSymbolAddress((void**)&gA, g_A);

    const int Mq = B_ * TQ_;    // 2048
    const int Mkv = B_ * TKV_;  // 16384

    // Mask normalization (tiny)
    detect_mask_kernel<<<1, 256>>>((const unsigned char*)mask);
    convert_mask_kernel<<<(B_ * TQ_ * TKV_) / (256 * 4), 256>>>(mask);

    // Projections
    gemm_bias_kernel<<<dim3(D_ / 64, Mq / 128), 256>>>(xq, Wq, bq, gQ, Mq, D_, D_);
    gemm_bias_kernel<<<dim3(D_ / 64, Mkv / 128), 256>>>(xkv, Wk, bk, gK, Mkv, D_, D_);
    gemm_bias_kernel<<<dim3(D_ / 64, Mkv / 128), 256>>>(xkv, Wv, bv, gV, Mkv, D_, D_);

    // Attention
    cudaFuncSetAttribute(flash_kernel, cudaFuncAttributeMaxDynamicSharedMemorySize,
                         FLASH_SMEM_BYTES);
    flash_kernel<<<dim3(TQ_ / 64, H_, B_), 256, FLASH_SMEM_BYTES>>>(gQ, gK, gV, gA);

    // Output projection
    gemm_bias_kernel<<<dim3(D_ / 64, Mq / 128), 256>>>(gA, Wo, bo, (float*)d_out,
                                                       Mq, D_, D_);
}

// round 7
// speedup vs baseline: 1.0461x; 1.0461x over previous
#include <cuda_runtime.h>

// Problem constants
#define B_   4
#define TQ_  512
#define TKV_ 4096
#define D_   1024
#define H_   8
#define HD_  128

typedef unsigned long long u64;

// ---- packed fp32x2 helpers (Blackwell FFMA2; ptxas never auto-fuses) ----
__device__ __forceinline__ u64 splat2(float v) {
    u64 r; asm("mov.b64 %0, {%1, %1};" : "=l"(r) : "f"(v)); return r;
}
__device__ __forceinline__ u64 ffma2(u64 a, u64 b, u64 c) {
    u64 d; asm("fma.rn.f32x2 %0, %1, %2, %3;" : "=l"(d) : "l"(a), "l"(b), "l"(c)); return d;
}
__device__ __forceinline__ u64 fmul2(u64 a, u64 b) {
    u64 d; asm("mul.rn.f32x2 %0, %1, %2;" : "=l"(d) : "l"(a), "l"(b)); return d;
}
__device__ __forceinline__ float2 unpk(u64 v) {
    float2 r; asm("mov.b64 {%0, %1}, %2;" : "=f"(r.x), "=f"(r.y) : "l"(v)); return r;
}

// Scratch (device globals; no allocation allowed)
__device__ float g_Q[(size_t)B_ * TQ_ * D_];
__device__ float g_K[(size_t)B_ * TKV_ * D_];
__device__ float g_V[(size_t)B_ * TKV_ * D_];
__device__ float g_A[(size_t)B_ * TQ_ * D_];
__device__ unsigned char g_M[(size_t)B_ * TQ_ * TKV_];
__device__ int g_mask_mode;   // 0=uint8, 1=int32, 2=float32

// ---------------------------------------------------------------------------
// Mask dtype detection (validated in R4).
// ---------------------------------------------------------------------------
__global__ void detect_mask_kernel(const unsigned char* __restrict__ m)
{
    __shared__ int s_weird, s_misal;
    if (threadIdx.x == 0) { s_weird = 0; s_misal = 0; }
    __syncthreads();
    int w = 0, ma = 0;
    for (int i = threadIdx.x * 4; i < 65536; i += 256 * 4) {
        uchar4 v = *(const uchar4*)(m + i);
        if (v.x > 1 || v.y > 1 || v.z > 1 || v.w > 1) w = 1;
        if (v.y | v.z | v.w) ma = 1;
    }
    if (w)  atomicOr(&s_weird, 1);
    if (ma) atomicOr(&s_misal, 1);
    __syncthreads();
    if (threadIdx.x == 0)
        g_mask_mode = s_weird ? 2 : (s_misal ? 0 : 1);
}

__global__ __launch_bounds__(256) void convert_mask_kernel(const void* __restrict__ src)
{
    const size_t i4 = ((size_t)blockIdx.x * blockDim.x + threadIdx.x) * 4;
    const int mode = g_mask_mode;
    uchar4 o;
    if (mode == 0) {
        uchar4 v = *(const uchar4*)((const unsigned char*)src + i4);
        o.x = v.x ? 1 : 0; o.y = v.y ? 1 : 0; o.z = v.z ? 1 : 0; o.w = v.w ? 1 : 0;
    } else if (mode == 1) {
        int4 v = *(const int4*)((const int*)src + i4);
        o.x = v.x ? 1 : 0; o.y = v.y ? 1 : 0; o.z = v.z ? 1 : 0; o.w = v.w ? 1 : 0;
    } else {
        float4 v = *(const float4*)((const float*)src + i4);
        o.x = (v.x != 0.f) ? 1 : 0; o.y = (v.y != 0.f) ? 1 : 0;
        o.z = (v.z != 0.f) ? 1 : 0; o.w = (v.w != 0.f) ? 1 : 0;
    }
    *(uchar4*)(g_M + i4) = o;
}

// ---------------------------------------------------------------------------
// GEMM: Y[M,N] = X[M,K] @ W[K,N] + bias[N]; BM=128, BN=64, BK=16, 256 thr.
// Inner loop in packed f32x2: A row-pairs load pre-packed from SMEM (LDS.128
// yields 2 f32x2 operands); B scalars splatted. 16 FFMA2/kstep vs 32 FFMA.
// ---------------------------------------------------------------------------
__global__ __launch_bounds__(256) void gemm_bias_kernel(
    const float* __restrict__ X, const float* __restrict__ W,
    const float* __restrict__ bias, float* __restrict__ Y,
    int M, int N, int K)
{
    __shared__ float As[16][128];   // As[k][m], m contiguous
    __shared__ float Bs[16][64];    // Bs[k][n]

    const int tid = threadIdx.x;
    const int tx = tid & 15;
    const int ty = tid >> 4;
    const int m0 = blockIdx.y * 128;
    const int n0 = blockIdx.x * 64;

    const int ar = tid >> 2;
    const int ac = (tid & 3) << 2;
    const int br = tid >> 4;
    const int bc = (tid & 15) << 2;

    const float* Xp  = X + (size_t)(m0 + ar) * K + ac;
    const float* Xp2 = Xp + (size_t)64 * K;
    const float* Wp  = W + (size_t)br * N + n0 + bc;

    u64 acc2[4][4] = {};   // [row-pair i2][col j]; rows ty*8+2*i2, +1

    float4 a0 = *(const float4*)(Xp);
    float4 a1 = *(const float4*)(Xp2);
    float4 b0 = *(const float4*)(Wp);

    for (int k0 = 0; k0 < K; k0 += 16) {
        __syncthreads();
        As[ac + 0][ar] = a0.x; As[ac + 1][ar] = a0.y;
        As[ac + 2][ar] = a0.z; As[ac + 3][ar] = a0.w;
        As[ac + 0][ar + 64] = a1.x; As[ac + 1][ar + 64] = a1.y;
        As[ac + 2][ar + 64] = a1.z; As[ac + 3][ar + 64] = a1.w;
        *(float4*)&Bs[br][bc] = b0;
        __syncthreads();

        if (k0 + 16 < K) {
            a0 = *(const float4*)(Xp + k0 + 16);
            a1 = *(const float4*)(Xp2 + k0 + 16);
            b0 = *(const float4*)(Wp + (size_t)(k0 + 16) * N);
        }

        #pragma unroll
        for (int kk = 0; kk < 16; kk++) {
            ulonglong2 aA = *(const ulonglong2*)&As[kk][ty * 8];      // pairs 0,1
            ulonglong2 aB = *(const ulonglong2*)&As[kk][ty * 8 + 4];  // pairs 2,3
            float4 bv = *(const float4*)&Bs[kk][tx * 4];
            u64 a2[4] = {aA.x, aA.y, aB.x, aB.y};
            u64 bs[4] = {splat2(bv.x), splat2(bv.y), splat2(bv.z), splat2(bv.w)};
            #pragma unroll
            for (int i2 = 0; i2 < 4; i2++)
                #pragma unroll
                for (int j = 0; j < 4; j++)
                    acc2[i2][j] = ffma2(a2[i2], bs[j], acc2[i2][j]);
        }
    }

    float4 bb = *(const float4*)(bias + n0 + (tx << 2));
    #pragma unroll
    for (int i2 = 0; i2 < 4; i2++) {
        float2 c0 = unpk(acc2[i2][0]);
        float2 c1 = unpk(acc2[i2][1]);
        float2 c2 = unpk(acc2[i2][2]);
        float2 c3 = unpk(acc2[i2][3]);
        float4 lo, hi;
        lo.x = c0.x + bb.x; lo.y = c1.x + bb.y; lo.z = c2.x + bb.z; lo.w = c3.x + bb.w;
        hi.x = c0.y + bb.x; hi.y = c1.y + bb.y; hi.z = c2.y + bb.z; hi.w = c3.y + bb.w;
        *(float4*)(Y + (size_t)(m0 + ty * 8 + 2 * i2)     * N + n0 + (tx << 2)) = lo;
        *(float4*)(Y + (size_t)(m0 + ty * 8 + 2 * i2 + 1) * N + n0 + (tx << 2)) = hi;
    }
}

// ---------------------------------------------------------------------------
// Flash attention, fp32, packed f32x2 inner loops.
// Block: one (b, h, 64-row q-tile). 256 threads (16x16).
// Score cols per thread: tx + 16*jj (conflict-free packed K loads, pitch 130).
// QK^T packs along d (horizontal add at end); PV packs along head-dim cols.
// ---------------------------------------------------------------------------
#define QK_PITCH 130
#define FLASH_SMEM_FLOATS (2 * 64 * QK_PITCH + 64 * 128 + 64 * 65)
#define FLASH_SMEM_BYTES  (FLASH_SMEM_FLOATS * 4)

__global__ __launch_bounds__(256) void flash_kernel(
    const float* __restrict__ Q, const float* __restrict__ Kg,
    const float* __restrict__ Vg, float* __restrict__ A)
{
    extern __shared__ float sm[];
    float* Qs = sm;                                     // [64][130]
    float* Ks = sm + 64 * QK_PITCH;                     // [64][130]
    float* Vs = sm + 2 * 64 * QK_PITCH;                 // [64][128]
    float* Ps = sm + 2 * 64 * QK_PITCH + 64 * 128;      // [64][65]  Ps[col][row]

    const int tid = threadIdx.x;
    const int tx = tid & 15;
    const int ty = tid >> 4;
    const int q0 = blockIdx.x * 64;
    const int h  = blockIdx.y;
    const int b  = blockIdx.z;

    const float SCALE = 0.08838834764831843f;  // 1/sqrt(128)
    const float NEG   = -1e30f;

    const float* Qb = Q  + ((size_t)b * TQ_ + q0) * D_ + h * HD_;
    const float* Kb = Kg + (size_t)b * TKV_ * D_ + h * HD_;
    const float* Vb = Vg + (size_t)b * TKV_ * D_ + h * HD_;
    const unsigned char* Mb = g_M + ((size_t)b * TQ_ + q0) * TKV_;

    // Load Q tile (64 x 128), scalar smem stores (pitch 130)
    #pragma unroll
    for (int r = 0; r < 8; r++) {
        int f = tid + 256 * r;
        int i = f >> 5;
        int d4 = (f & 31) << 2;
        float4 v = *(const float4*)(Qb + (size_t)i * D_ + d4);
        float* q = Qs + i * QK_PITCH + d4;
        q[0] = v.x; q[1] = v.y; q[2] = v.z; q[3] = v.w;
    }

    float m[4], l[4];
    u64 acc2[4][4];   // [q-row ii][col-pair]
    #pragma unroll
    for (int ii = 0; ii < 4; ii++) {
        m[ii] = -INFINITY;
        l[ii] = 0.0f;
        #pragma unroll
        for (int c = 0; c < 4; c++) acc2[ii][c] = 0ull;
    }

    for (int t = 0; t < TKV_ / 64; t++) {
        const int kv0 = t * 64;
        __syncthreads();

        const float* Kt = Kb + (size_t)kv0 * D_;
        const float* Vt = Vb + (size_t)kv0 * D_;
        #pragma unroll
        for (int r = 0; r < 8; r++) {
            int f = tid + 256 * r;
            int j = f >> 5;
            int d4 = (f & 31) << 2;
            float4 kv = *(const float4*)(Kt + (size_t)j * D_ + d4);
            float* kp = Ks + j * QK_PITCH + d4;
            kp[0] = kv.x; kp[1] = kv.y; kp[2] = kv.z; kp[3] = kv.w;
            float4 vv = *(const float4*)(Vt + (size_t)j * D_ + d4);
            *(float4*)(Vs + j * 128 + d4) = vv;
        }
        __syncthreads();

        // S = Q @ K^T, packed along d. Thread cols: tx + 16*jj.
        u64 s2[4][4] = {};
        const float* qrow = Qs + (ty * 4) * QK_PITCH;
        const float* kcol = Ks + tx * QK_PITCH;
        #pragma unroll 4
        for (int d = 0; d < 128; d += 2) {
            u64 q2[4], k2[4];
            #pragma unroll
            for (int ii = 0; ii < 4; ii++)
                q2[ii] = *(const u64*)&qrow[ii * QK_PITCH + d];
            #pragma unroll
            for (int jj = 0; jj < 4; jj++)
                k2[jj] = *(const u64*)&kcol[jj * 16 * QK_PITCH + d];
            #pragma unroll
            for (int ii = 0; ii < 4; ii++)
                #pragma unroll
                for (int jj = 0; jj < 4; jj++)
                    s2[ii][jj] = ffma2(q2[ii], k2[jj], s2[ii][jj]);
        }

        // Horizontal add + mask + scale. Mask col = kv0 + tx + 16*jj.
        float s[4][4];
        #pragma unroll
        for (int ii = 0; ii < 4; ii++) {
            const unsigned char* mrow = Mb + (size_t)(ty * 4 + ii) * TKV_ + kv0 + tx;
            #pragma unroll
            for (int jj = 0; jj < 4; jj++) {
                float2 p = unpk(s2[ii][jj]);
                float sv = p.x + p.y;
                s[ii][jj] = mrow[16 * jj] ? sv * SCALE : NEG;
            }
        }

        // Online softmax (reduction across 16 tx lanes)
        #pragma unroll
        for (int ii = 0; ii < 4; ii++) {
            float rm = fmaxf(fmaxf(s[ii][0], s[ii][1]), fmaxf(s[ii][2], s[ii][3]));
            #pragma unroll
            for (int o = 1; o < 16; o <<= 1)
                rm = fmaxf(rm, __shfl_xor_sync(0xffffffffu, rm, o));
            float mnew = fmaxf(m[ii], rm);
            float corr = __expf(m[ii] - mnew);
            m[ii] = mnew;
            float rs = 0.0f;
            #pragma unroll
            for (int jj = 0; jj < 4; jj++) {
                float p = __expf(s[ii][jj] - mnew);
                s[ii][jj] = p;
                rs += p;
            }
            #pragma unroll
            for (int o = 1; o < 16; o <<= 1)
                rs += __shfl_xor_sync(0xffffffffu, rs, o);
            l[ii] = l[ii] * corr + rs;
            u64 corr2 = splat2(corr);
            #pragma unroll
            for (int c = 0; c < 4; c++) acc2[ii][c] = fmul2(acc2[ii][c], corr2);
        }

        // Write P transposed: Ps[col][row], col = tx + 16*jj
        #pragma unroll
        for (int jj = 0; jj < 4; jj++)
            #pragma unroll
            for (int ii = 0; ii < 4; ii++)
                Ps[(tx + 16 * jj) * 65 + ty * 4 + ii] = s[ii][jj];
        __syncthreads();

        // O += P @ V, packed along head-dim cols.
        #pragma unroll 4
        for (int j = 0; j < 64; j++) {
            u64 p2[4];
            #pragma unroll
            for (int ii = 0; ii < 4; ii++)
                p2[ii] = splat2(Ps[j * 65 + ty * 4 + ii]);
            ulonglong2 va = *(const ulonglong2*)&Vs[j * 128 + tx * 4];
            ulonglong2 vb = *(const ulonglong2*)&Vs[j * 128 + 64 + tx * 4];
            #pragma unroll
            for (int ii = 0; ii < 4; ii++) {
                acc2[ii][0] = ffma2(p2[ii], va.x, acc2[ii][0]);
                acc2[ii][1] = ffma2(p2[ii], va.y, acc2[ii][1]);
                acc2[ii][2] = ffma2(p2[ii], vb.x, acc2[ii][2]);
                acc2[ii][3] = ffma2(p2[ii], vb.y, acc2[ii][3]);
            }
        }
    }

    // Epilogue: normalize; wipe fully-masked rows (row-max still at -1e30).
    #pragma unroll
    for (int ii = 0; ii < 4; ii++) {
        float inv = (m[ii] < -1e29f) ? 0.0f : (1.0f / l[ii]);
        int qi = q0 + ty * 4 + ii;
        float* out = A + ((size_t)b * TQ_ + qi) * D_ + h * HD_ + tx * 4;
        float2 c0 = unpk(acc2[ii][0]);
        float2 c1 = unpk(acc2[ii][1]);
        float2 c2 = unpk(acc2[ii][2]);
        float2 c3 = unpk(acc2[ii][3]);
        float4 o1, o2;
        o1.x = c0.x * inv; o1.y = c0.y * inv; o1.z = c1.x * inv; o1.w = c1.y * inv;
        o2.x = c2.x * inv; o2.y = c2.y * inv; o2.z = c3.x * inv; o2.w = c3.y * inv;
        *(float4*)out = o1;
        *(float4*)(out + 64) = o2;
    }
}

// ---------------------------------------------------------------------------
// Launch: mask normalize + Q/K/V projections -> flash attention -> out proj.
// ---------------------------------------------------------------------------
extern "C" void kernel_launch(void* const* d_in, const int* in_sizes, int n_in,
                              void* d_out, int out_size)
{
    const float* xq   = (const float*)d_in[0];
    const float* xkv  = (const float*)d_in[1];
    const void*  mask = d_in[2];
    const float* Wq = (const float*)d_in[3];
    const float* bq = (const float*)d_in[4];
    const float* Wk = (const float*)d_in[5];
    const float* bk = (const float*)d_in[6];
    const float* Wv = (const float*)d_in[7];
    const float* bv = (const float*)d_in[8];
    const float* Wo = (const float*)d_in[9];
    const float* bo = (const float*)d_in[10];

    float *gQ, *gK, *gV, *gA;
    cudaGetSymbolAddress((void**)&gQ, g_Q);
    cudaGetSymbolAddress((void**)&gK, g_K);
    cudaGetSymbolAddress((void**)&gV, g_V);
    cudaGetSymbolAddress((void**)&gA, g_A);

    const int Mq = B_ * TQ_;    // 2048
    const int Mkv = B_ * TKV_;  // 16384

    // Mask normalization
    detect_mask_kernel<<<1, 256>>>((const unsigned char*)mask);
    convert_mask_kernel<<<(B_ * TQ_ * TKV_) / (256 * 4), 256>>>(mask);

    // Projections
    gemm_bias_kernel<<<dim3(D_ / 64, Mq / 128), 256>>>(xq, Wq, bq, gQ, Mq, D_, D_);
    gemm_bias_kernel<<<dim3(D_ / 64, Mkv / 128), 256>>>(xkv, Wk, bk, gK, Mkv, D_, D_);
    gemm_bias_kernel<<<dim3(D_ / 64, Mkv / 128), 256>>>(xkv, Wv, bv, gV, Mkv, D_, D_);

    // Attention
    cudaFuncSetAttribute(flash_kernel, cudaFuncAttributeMaxDynamicSharedMemorySize,
                         FLASH_SMEM_BYTES);
    flash_kernel<<<dim3(TQ_ / 64, H_, B_), 256, FLASH_SMEM_BYTES>>>(gQ, gK, gV, gA);

    // Output projection
    gemm_bias_kernel<<<dim3(D_ / 64, Mq / 128), 256>>>(gA, Wo, bo, (float*)d_out,
                                                       Mq, D_, D_);
}

// round 11
// speedup vs baseline: 1.3218x; 1.2635x over previous
#include <cuda_runtime.h>
#include <cuda_bf16.h>

// Problem constants
#define B_   4
#define TQ_  512
#define TKV_ 4096
#define D_   1024
#define H_   8
#define HD_  128

typedef unsigned long long u64;
typedef unsigned int u32;

// ---- packed fp32x2 helpers (flash kernel) ----
__device__ __forceinline__ u64 splat2(float v) {
    u64 r; asm("mov.b64 %0, {%1, %1};" : "=l"(r) : "f"(v)); return r;
}
__device__ __forceinline__ u64 ffma2(u64 a, u64 b, u64 c) {
    u64 d; asm("fma.rn.f32x2 %0, %1, %2, %3;" : "=l"(d) : "l"(a), "l"(b), "l"(c)); return d;
}
__device__ __forceinline__ u64 fmul2(u64 a, u64 b) {
    u64 d; asm("mul.rn.f32x2 %0, %1, %2;" : "=l"(d) : "l"(a), "l"(b)); return d;
}
__device__ __forceinline__ float2 unpk(u64 v) {
    float2 r; asm("mov.b64 {%0, %1}, %2;" : "=f"(r.x), "=f"(r.y) : "l"(v)); return r;
}

// Scratch (device globals; no allocation allowed)
__device__ float g_Q[(size_t)B_ * TQ_ * D_];
__device__ float g_K[(size_t)B_ * TKV_ * D_];
__device__ float g_V[(size_t)B_ * TKV_ * D_];
__device__ float g_A[(size_t)B_ * TQ_ * D_];
__device__ unsigned char g_M[(size_t)B_ * TQ_ * TKV_];
__device__ int g_mask_mode;   // 0=uint8, 1=int32, 2=float32

// ---------------------------------------------------------------------------
// Mask dtype detection + canonicalization (validated R4/R7).
// ---------------------------------------------------------------------------
__global__ void detect_mask_kernel(const unsigned char* __restrict__ m)
{
    __shared__ int s_weird, s_misal;
    if (threadIdx.x == 0) { s_weird = 0; s_misal = 0; }
    __syncthreads();
    int w = 0, ma = 0;
    for (int i = threadIdx.x * 4; i < 65536; i += 256 * 4) {
        uchar4 v = *(const uchar4*)(m + i);
        if (v.x > 1 || v.y > 1 || v.z > 1 || v.w > 1) w = 1;
        if (v.y | v.z | v.w) ma = 1;
    }
    if (w)  atomicOr(&s_weird, 1);
    if (ma) atomicOr(&s_misal, 1);
    __syncthreads();
    if (threadIdx.x == 0)
        g_mask_mode = s_weird ? 2 : (s_misal ? 0 : 1);
}

__global__ __launch_bounds__(256) void convert_mask_kernel(const void* __restrict__ src)
{
    const size_t i4 = ((size_t)blockIdx.x * blockDim.x + threadIdx.x) * 4;
    const int mode = g_mask_mode;
    uchar4 o;
    if (mode == 0) {
        uchar4 v = *(const uchar4*)((const unsigned char*)src + i4);
        o.x = v.x ? 1 : 0; o.y = v.y ? 1 : 0; o.z = v.z ? 1 : 0; o.w = v.w ? 1 : 0;
    } else if (mode == 1) {
        int4 v = *(const int4*)((const int*)src + i4);
        o.x = v.x ? 1 : 0; o.y = v.y ? 1 : 0; o.z = v.z ? 1 : 0; o.w = v.w ? 1 : 0;
    } else {
        float4 v = *(const float4*)((const float*)src + i4);
        o.x = (v.x != 0.f) ? 1 : 0; o.y = (v.y != 0.f) ? 1 : 0;
        o.z = (v.z != 0.f) ? 1 : 0; o.w = (v.w != 0.f) ? 1 : 0;
    }
    *(uchar4*)(g_M + i4) = o;
}

// ---------------------------------------------------------------------------
// Tensor-core GEMM with bf16 split precision (3-product: hh + hl + lh).
// Y[M,N] = X[M,K] @ W[K,N] + bias.  BM=128, BN=128, BK=32; 256 thr = 8 warps
// in 2(m)x4(n); warp tile 64x32 via mma.sync.m16n8k16 (4 m-frags x 4 n-frags).
// SMEM tiles: A[m][k] (hi/lo), B[n][k] (hi/lo, transposed on store), pitch 40
// bf16 -> fragment LDS.32 pattern {20*r + t mod 32} covers all banks once.
// ---------------------------------------------------------------------------
#define PITCH 40

__device__ __forceinline__ void split2(float x0, float x1, u32& hi, u32& lo) {
    __nv_bfloat16 h0 = __float2bfloat16_rn(x0);
    __nv_bfloat16 h1 = __float2bfloat16_rn(x1);
    __nv_bfloat16 l0 = __float2bfloat16_rn(x0 - __bfloat162float(h0));
    __nv_bfloat16 l1 = __float2bfloat16_rn(x1 - __bfloat162float(h1));
    hi = ((u32)__bfloat16_as_ushort(h1) << 16) | (u32)__bfloat16_as_ushort(h0);
    lo = ((u32)__bfloat16_as_ushort(l1) << 16) | (u32)__bfloat16_as_ushort(l0);
}

__device__ __forceinline__ void mma16816(float* c, const u32* a, const u32* b) {
    asm volatile(
        "mma.sync.aligned.m16n8k16.row.col.f32.bf16.bf16.f32 "
        "{%0,%1,%2,%3}, {%4,%5,%6,%7}, {%8,%9}, {%0,%1,%2,%3};\n"
        : "+f"(c[0]), "+f"(c[1]), "+f"(c[2]), "+f"(c[3])
        : "r"(a[0]), "r"(a[1]), "r"(a[2]), "r"(a[3]), "r"(b[0]), "r"(b[1]));
}

__global__ __launch_bounds__(256) void gemm_mma_kernel(
    const float* __restrict__ X, const float* __restrict__ W,
    const float* __restrict__ bias, float* __restrict__ Y,
    int M, int N, int K)
{
    __shared__ __align__(16) __nv_bfloat16 Ah[128][PITCH];
    __shared__ __align__(16) __nv_bfloat16 Al[128][PITCH];
    __shared__ __align__(16) __nv_bfloat16 Bh[128][PITCH];
    __shared__ __align__(16) __nv_bfloat16 Bl[128][PITCH];

    const int tid  = threadIdx.x;
    const int lane = tid & 31;
    const int warp = tid >> 5;
    const int wm   = warp >> 2;      // 0..1
    const int wn   = warp & 3;       // 0..3
    const int gid  = lane >> 2;      // 0..7
    const int tig  = lane & 3;       // 0..3
    const int m0   = blockIdx.y * 128;
    const int n0   = blockIdx.x * 128;

    // Global-load mappings
    const int am  = tid >> 1;            // 0..127
    const int ak0 = (tid & 1) << 4;      // 0 or 16
    const int bn  = tid & 127;           // 0..127
    const int bk0 = (tid >> 7) << 4;     // 0 or 16

    const float* Xp = X + (size_t)(m0 + am) * K + ak0;

    float acc[4][4][4] = {};
    float4 areg[4];
    float  breg[16];

    // Prefetch ktile 0
    #pragma unroll
    for (int j = 0; j < 4; j++)
        areg[j] = *(const float4*)(Xp + j * 4);
    #pragma unroll
    for (int j = 0; j < 16; j++)
        breg[j] = W[(size_t)(bk0 + j) * N + n0 + bn];

    for (int k0 = 0; k0 < K; k0 += 32) {
        __syncthreads();   // previous compute done reading smem

        // Store A tile (split hi/lo): 16 bf16 contiguous per thread
        {
            u32 h[8], l[8];
            #pragma unroll
            for (int j = 0; j < 4; j++) {
                split2(areg[j].x, areg[j].y, h[2*j],   l[2*j]);
                split2(areg[j].z, areg[j].w, h[2*j+1], l[2*j+1]);
            }
            uint4* dh = (uint4*)&Ah[am][ak0];
            uint4* dl = (uint4*)&Al[am][ak0];
            dh[0] = make_uint4(h[0], h[1], h[2], h[3]);
            dh[1] = make_uint4(h[4], h[5], h[6], h[7]);
            dl[0] = make_uint4(l[0], l[1], l[2], l[3]);
            dl[1] = make_uint4(l[4], l[5], l[6], l[7]);
        }
        // Store B tile transposed (split hi/lo): B[n][k], 16 bf16 contiguous
        {
            u32 h[8], l[8];
            #pragma unroll
            for (int j = 0; j < 8; j++)
                split2(breg[2*j], breg[2*j+1], h[j], l[j]);
            uint4* dh = (uint4*)&Bh[bn][bk0];
            uint4* dl = (uint4*)&Bl[bn][bk0];
            dh[0] = make_uint4(h[0], h[1], h[2], h[3]);
            dh[1] = make_uint4(h[4], h[5], h[6], h[7]);
            dl[0] = make_uint4(l[0], l[1], l[2], l[3]);
            dl[1] = make_uint4(l[4], l[5], l[6], l[7]);
        }
        __syncthreads();

        // Prefetch next ktile while computing
        if (k0 + 32 < K) {
            #pragma unroll
            for (int j = 0; j < 4; j++)
                areg[j] = *(const float4*)(Xp + k0 + 32 + j * 4);
            #pragma unroll
            for (int j = 0; j < 16; j++)
                breg[j] = W[(size_t)(k0 + 32 + bk0 + j) * N + n0 + bn];
        }

        #pragma unroll
        for (int ks = 0; ks < 32; ks += 16) {
            // B fragments for 4 n-frags (hi/lo)
            u32 bh[4][2], bl[4][2];
            #pragma unroll
            for (int nf = 0; nf < 4; nf++) {
                int n = wn * 32 + nf * 8 + gid;
                bh[nf][0] = *(const u32*)&Bh[n][ks + tig * 2];
                bh[nf][1] = *(const u32*)&Bh[n][ks + 8 + tig * 2];
                bl[nf][0] = *(const u32*)&Bl[n][ks + tig * 2];
                bl[nf][1] = *(const u32*)&Bl[n][ks + 8 + tig * 2];
            }
            #pragma unroll
            for (int mf = 0; mf < 4; mf++) {
                int m = wm * 64 + mf * 16 + gid;
                u32 ah[4], al[4];
                ah[0] = *(const u32*)&Ah[m][ks + tig * 2];
                ah[1] = *(const u32*)&Ah[m + 8][ks + tig * 2];
                ah[2] = *(const u32*)&Ah[m][ks + 8 + tig * 2];
                ah[3] = *(const u32*)&Ah[m + 8][ks + 8 + tig * 2];
                al[0] = *(const u32*)&Al[m][ks + tig * 2];
                al[1] = *(const u32*)&Al[m + 8][ks + tig * 2];
                al[2] = *(const u32*)&Al[m][ks + 8 + tig * 2];
                al[3] = *(const u32*)&Al[m + 8][ks + 8 + tig * 2];
                #pragma unroll
                for (int nf = 0; nf < 4; nf++) {
                    mma16816(acc[mf][nf], ah, bh[nf]);   // hi*hi
                    mma16816(acc[mf][nf], ah, bl[nf]);   // hi*lo
                    mma16816(acc[mf][nf], al, bh[nf]);   // lo*hi
                }
            }
        }
    }

    // Epilogue: bias + store (c0,c1 row gid; c2,c3 row gid+8; cols 2*tig,+1)
    #pragma unroll
    for (int mf = 0; mf < 4; mf++) {
        int row = m0 + wm * 64 + mf * 16 + gid;
        #pragma unroll
        for (int nf = 0; nf < 4; nf++) {
            int col = n0 + wn * 32 + nf * 8 + tig * 2;
            float2 bb = *(const float2*)(bias + col);
            float2 v0, v1;
            v0.x = acc[mf][nf][0] + bb.x; v0.y = acc[mf][nf][1] + bb.y;
            v1.x = acc[mf][nf][2] + bb.x; v1.y = acc[mf][nf][3] + bb.y;
            *(float2*)(Y + (size_t)row * N + col) = v0;
            *(float2*)(Y + (size_t)(row + 8) * N + col) = v1;
        }
    }
}

// ---------------------------------------------------------------------------
// Flash attention, fp32 packed f32x2 (validated R7). Unchanged.
// ---------------------------------------------------------------------------
#define QK_PITCH 130
#define FLASH_SMEM_FLOATS (2 * 64 * QK_PITCH + 64 * 128 + 64 * 65)
#define FLASH_SMEM_BYTES  (FLASH_SMEM_FLOATS * 4)

__global__ __launch_bounds__(256) void flash_kernel(
    const float* __restrict__ Q, const float* __restrict__ Kg,
    const float* __restrict__ Vg, float* __restrict__ A)
{
    extern __shared__ float sm[];
    float* Qs = sm;                                     // [64][130]
    float* Ks = sm + 64 * QK_PITCH;                     // [64][130]
    float* Vs = sm + 2 * 64 * QK_PITCH;                 // [64][128]
    float* Ps = sm + 2 * 64 * QK_PITCH + 64 * 128;      // [64][65]  Ps[col][row]

    const int tid = threadIdx.x;
    const int tx = tid & 15;
    const int ty = tid >> 4;
    const int q0 = blockIdx.x * 64;
    const int h  = blockIdx.y;
    const int b  = blockIdx.z;

    const float SCALE = 0.08838834764831843f;  // 1/sqrt(128)
    const float NEG   = -1e30f;

    const float* Qb = Q  + ((size_t)b * TQ_ + q0) * D_ + h * HD_;
    const float* Kb = Kg + (size_t)b * TKV_ * D_ + h * HD_;
    const float* Vb = Vg + (size_t)b * TKV_ * D_ + h * HD_;
    const unsigned char* Mb = g_M + ((size_t)b * TQ_ + q0) * TKV_;

    #pragma unroll
    for (int r = 0; r < 8; r++) {
        int f = tid + 256 * r;
        int i = f >> 5;
        int d4 = (f & 31) << 2;
        float4 v = *(const float4*)(Qb + (size_t)i * D_ + d4);
        float* q = Qs + i * QK_PITCH + d4;
        q[0] = v.x; q[1] = v.y; q[2] = v.z; q[3] = v.w;
    }

    float m[4], l[4];
    u64 acc2[4][4];
    #pragma unroll
    for (int ii = 0; ii < 4; ii++) {
        m[ii] = -INFINITY;
        l[ii] = 0.0f;
        #pragma unroll
        for (int c = 0; c < 4; c++) acc2[ii][c] = 0ull;
    }

    for (int t = 0; t < TKV_ / 64; t++) {
        const int kv0 = t * 64;
        __syncthreads();

        const float* Kt = Kb + (size_t)kv0 * D_;
        const float* Vt = Vb + (size_t)kv0 * D_;
        #pragma unroll
        for (int r = 0; r < 8; r++) {
            int f = tid + 256 * r;
            int j = f >> 5;
            int d4 = (f & 31) << 2;
            float4 kv = *(const float4*)(Kt + (size_t)j * D_ + d4);
            float* kp = Ks + j * QK_PITCH + d4;
            kp[0] = kv.x; kp[1] = kv.y; kp[2] = kv.z; kp[3] = kv.w;
            float4 vv = *(const float4*)(Vt + (size_t)j * D_ + d4);
            *(float4*)(Vs + j * 128 + d4) = vv;
        }
        __syncthreads();

        u64 s2[4][4] = {};
        const float* qrow = Qs + (ty * 4) * QK_PITCH;
        const float* kcol = Ks + tx * QK_PITCH;
        #pragma unroll 4
        for (int d = 0; d < 128; d += 2) {
            u64 q2[4], k2[4];
            #pragma unroll
            for (int ii = 0; ii < 4; ii++)
                q2[ii] = *(const u64*)&qrow[ii * QK_PITCH + d];
            #pragma unroll
            for (int jj = 0; jj < 4; jj++)
                k2[jj] = *(const u64*)&kcol[jj * 16 * QK_PITCH + d];
            #pragma unroll
            for (int ii = 0; ii < 4; ii++)
                #pragma unroll
                for (int jj = 0; jj < 4; jj++)
                    s2[ii][jj] = ffma2(q2[ii], k2[jj], s2[ii][jj]);
        }

        float s[4][4];
        #pragma unroll
        for (int ii = 0; ii < 4; ii++) {
            const unsigned char* mrow = Mb + (size_t)(ty * 4 + ii) * TKV_ + kv0 + tx;
            #pragma unroll
            for (int jj = 0; jj < 4; jj++) {
                float2 p = unpk(s2[ii][jj]);
                float sv = p.x + p.y;
                s[ii][jj] = mrow[16 * jj] ? sv * SCALE : NEG;
            }
        }

        #pragma unroll
        for (int ii = 0; ii < 4; ii++) {
            float rm = fmaxf(fmaxf(s[ii][0], s[ii][1]), fmaxf(s[ii][2], s[ii][3]));
            #pragma unroll
            for (int o = 1; o < 16; o <<= 1)
                rm = fmaxf(rm, __shfl_xor_sync(0xffffffffu, rm, o));
            float mnew = fmaxf(m[ii], rm);
            float corr = __expf(m[ii] - mnew);
            m[ii] = mnew;
            float rs = 0.0f;
            #pragma unroll
            for (int jj = 0; jj < 4; jj++) {
                float p = __expf(s[ii][jj] - mnew);
                s[ii][jj] = p;
                rs += p;
            }
            #pragma unroll
            for (int o = 1; o < 16; o <<= 1)
                rs += __shfl_xor_sync(0xffffffffu, rs, o);
            l[ii] = l[ii] * corr + rs;
            u64 corr2 = splat2(corr);
            #pragma unroll
            for (int c = 0; c < 4; c++) acc2[ii][c] = fmul2(acc2[ii][c], corr2);
        }

        #pragma unroll
        for (int jj = 0; jj < 4; jj++)
            #pragma unroll
            for (int ii = 0; ii < 4; ii++)
                Ps[(tx + 16 * jj) * 65 + ty * 4 + ii] = s[ii][jj];
        __syncthreads();

        #pragma unroll 4
        for (int j = 0; j < 64; j++) {
            u64 p2[4];
            #pragma unroll
            for (int ii = 0; ii < 4; ii++)
                p2[ii] = splat2(Ps[j * 65 + ty * 4 + ii]);
            ulonglong2 va = *(const ulonglong2*)&Vs[j * 128 + tx * 4];
            ulonglong2 vb = *(const ulonglong2*)&Vs[j * 128 + 64 + tx * 4];
            #pragma unroll
            for (int ii = 0; ii < 4; ii++) {
                acc2[ii][0] = ffma2(p2[ii], va.x, acc2[ii][0]);
                acc2[ii][1] = ffma2(p2[ii], va.y, acc2[ii][1]);
                acc2[ii][2] = ffma2(p2[ii], vb.x, acc2[ii][2]);
                acc2[ii][3] = ffma2(p2[ii], vb.y, acc2[ii][3]);
            }
        }
    }

    #pragma unroll
    for (int ii = 0; ii < 4; ii++) {
        float inv = (m[ii] < -1e29f) ? 0.0f : (1.0f / l[ii]);
        int qi = q0 + ty * 4 + ii;
        float* out = A + ((size_t)b * TQ_ + qi) * D_ + h * HD_ + tx * 4;
        float2 c0 = unpk(acc2[ii][0]);
        float2 c1 = unpk(acc2[ii][1]);
        float2 c2 = unpk(acc2[ii][2]);
        float2 c3 = unpk(acc2[ii][3]);
        float4 o1, o2;
        o1.x = c0.x * inv; o1.y = c0.y * inv; o1.z = c1.x * inv; o1.w = c1.y * inv;
        o2.x = c2.x * inv; o2.y = c2.y * inv; o2.z = c3.x * inv; o2.w = c3.y * inv;
        *(float4*)out = o1;
        *(float4*)(out + 64) = o2;
    }
}

// ---------------------------------------------------------------------------
// Launch
// ---------------------------------------------------------------------------
extern "C" void kernel_launch(void* const* d_in, const int* in_sizes, int n_in,
                              void* d_out, int out_size)
{
    const float* xq   = (const float*)d_in[0];
    const float* xkv  = (const float*)d_in[1];
    const void*  mask = d_in[2];
    const float* Wq = (const float*)d_in[3];
    const float* bq = (const float*)d_in[4];
    const float* Wk = (const float*)d_in[5];
    const float* bk = (const float*)d_in[6];
    const float* Wv = (const float*)d_in[7];
    const float* bv = (const float*)d_in[8];
    const float* Wo = (const float*)d_in[9];
    const float* bo = (const float*)d_in[10];

    float *gQ, *gK, *gV, *gA;
    cudaGetSymbolAddress((void**)&gQ, g_Q);
    cudaGetSymbolAddress((void**)&gK, g_K);
    cudaGetSymbolAddress((void**)&gV, g_V);
    cudaGetSymbolAddress((void**)&gA, g_A);

    const int Mq = B_ * TQ_;    // 2048
    const int Mkv = B_ * TKV_;  // 16384

    // Mask normalization
    detect_mask_kernel<<<1, 256>>>((const unsigned char*)mask);
    convert_mask_kernel<<<(B_ * TQ_ * TKV_) / (256 * 4), 256>>>(mask);

    // Projections on tensor cores (bf16 split precision)
    gemm_mma_kernel<<<dim3(D_ / 128, Mq / 128), 256>>>(xq, Wq, bq, gQ, Mq, D_, D_);
    gemm_mma_kernel<<<dim3(D_ / 128, Mkv / 128), 256>>>(xkv, Wk, bk, gK, Mkv, D_, D_);
    gemm_mma_kernel<<<dim3(D_ / 128, Mkv / 128), 256>>>(xkv, Wv, bv, gV, Mkv, D_, D_);

    // Attention
    cudaFuncSetAttribute(flash_kernel, cudaFuncAttributeMaxDynamicSharedMemorySize,
                         FLASH_SMEM_BYTES);
    flash_kernel<<<dim3(TQ_ / 64, H_, B_), 256, FLASH_SMEM_BYTES>>>(gQ, gK, gV, gA);

    // Output projection
    gemm_mma_kernel<<<dim3(D_ / 128, Mq / 128), 256>>>(gA, Wo, bo, (float*)d_out,
                                                       Mq, D_, D_);
}